// round 9
// baseline (speedup 1.0000x reference)
#include <cuda_runtime.h>
#include <cuda_bf16.h>
#include <cuda_fp16.h>
#include <cstdint>
#include <cstddef>

// Problem constants
#define V_NODES   25000
#define E_EDGES   100000
#define NODE_IN   74
#define EDGE_IN   12
#define OUT_DIM   64
#define EHID      128
#define NSTEPS    6
#define N_EW      4096        // OUT*OUT

#define M_TILES   782          // ceil(100000/128)
#define N_TILES   32
#define NTILES    (M_TILES * N_TILES)
#define NPERS     296          // 2 persistent CTAs per SM x 148 SMs

// ---------------------------------------------------------------------------
// Scratch (__device__ globals -- the sanctioned scratch mechanism)
// ---------------------------------------------------------------------------
__device__ float  g_h  [V_NODES * OUT_DIM];                 // 6.4 MB
__device__ float  g_agg[V_NODES * OUT_DIM];                 // 6.4 MB
__device__ __align__(256) __half g_zh [E_EDGES * EHID];     // 25.6 MB  z (fp16)
__device__ __align__(256) __half g_Wt [N_EW * EHID];        // 1 MB     We2^T (fp16)
__device__ __align__(256) __half g_ewh[(size_t)E_EDGES * N_EW]; // 819 MB ew (fp16)

__device__ __forceinline__ uint32_t smem_to_u32(const void* p) {
    uint32_t a;
    asm("{ .reg .u64 t; cvta.to.shared.u64 t, %1; cvt.u32.u64 %0, t; }" : "=r"(a) : "l"(p));
    return a;
}

// ---------------------------------------------------------------------------
// Kernel 1: h = relu(node_feats @ Wp + bp)      [25000 x 74] @ [74 x 64]
// ---------------------------------------------------------------------------
__global__ void k_project(const float* __restrict__ nf,
                          const float* __restrict__ Wp,
                          const float* __restrict__ bp) {
    int v = blockIdx.x;
    int o = threadIdx.x;                 // 64 threads
    __shared__ float s[NODE_IN];
    for (int i = o; i < NODE_IN; i += OUT_DIM) s[i] = nf[v * NODE_IN + i];
    __syncthreads();
    float acc = bp[o];
    #pragma unroll
    for (int i = 0; i < NODE_IN; i++) acc = fmaf(s[i], Wp[i * OUT_DIM + o], acc);
    g_h[v * OUT_DIM + o] = fmaxf(acc, 0.0f);
}

// ---------------------------------------------------------------------------
// Kernel 2: z = relu(edge_feats @ We1 + be1) -> fp16    [100000 x 12] @ [12 x 128]
// ---------------------------------------------------------------------------
__global__ void k_edge1(const float* __restrict__ ef,
                        const float* __restrict__ We1,
                        const float* __restrict__ be1) {
    int e = blockIdx.x;
    int k = threadIdx.x;                 // 128 threads
    __shared__ float s[EDGE_IN];
    if (k < EDGE_IN) s[k] = ef[e * EDGE_IN + k];
    __syncthreads();
    float acc = be1[k];
    #pragma unroll
    for (int j = 0; j < EDGE_IN; j++) acc = fmaf(s[j], We1[j * EHID + k], acc);
    g_zh[e * EHID + k] = __float2half_rn(fmaxf(acc, 0.0f));
}

// ---------------------------------------------------------------------------
// Kernel 2b: Wt[n][k] = (half)We2[k][n]   (tiny one-time transpose, 1 MB out)
// ---------------------------------------------------------------------------
__global__ void k_transpose(const float* __restrict__ We2) {
    int n = blockIdx.x;                  // 4096
    int k = threadIdx.x;                 // 128
    g_Wt[n * EHID + k] = __float2half_rn(We2[(size_t)k * N_EW + n]);
}

// ---------------------------------------------------------------------------
// Kernel 3: PERSISTENT HMMA fp16 GEMM  ew = z @ We2 + be2 -> fp16
// 296 CTAs (2/SM) loop over all 25024 tiles. Per tile: K=128 in 2 cp.async
// double-buffered chunks. The NEXT tile's cp.async loads are issued BEFORE the
// current tile's epilogue stores, overlapping the DRAM write drain with the
// next tile's loads + MMA. Dedicated epilogue buffer (Cs) disjoint from the
// cp.async stage buffers. Smem 106.5+ KB/CTA -> 2 CTAs/SM.
// ---------------------------------------------------------------------------
#define BK        64
#define AS        72                               // halves per smem row (+pad)
#define STAGE_SZ  (128 * AS * 2)                   // 18432 B (one A or B buffer)
#define A0_OFF    0
#define B0_OFF    STAGE_SZ
#define A1_OFF    (2 * STAGE_SZ)
#define B1_OFF    (3 * STAGE_SZ)
#define C_OFF     (4 * STAGE_SZ)                   // 73728, 128 x 136 halves
#define CS        136
#define BIAS_OFF  (C_OFF + 128 * CS * 2)           // 108544
#define GEMM_SMEM (BIAS_OFF + 512)                 // 109056

__device__ __forceinline__ void stmatrix_x4(uint32_t addr, uint32_t r0, uint32_t r1,
                                            uint32_t r2, uint32_t r3) {
    asm volatile("stmatrix.sync.aligned.m8n8.x4.shared.b16 [%0], {%1,%2,%3,%4};"
                 :: "r"(addr), "r"(r0), "r"(r1), "r"(r2), "r"(r3) : "memory");
}

// issue cp.async loads for one tile (both K-chunks, 2 commit groups)
__device__ __forceinline__ void issue_tile_loads(uint32_t sb, int tid, int m0, int n0) {
    #pragma unroll
    for (int stage = 0; stage < 2; stage++) {
        int kc = stage * BK;
        uint32_t aoff = sb + (stage ? A1_OFF : A0_OFF);
        uint32_t boff = sb + (stage ? B1_OFF : B0_OFF);
        #pragma unroll
        for (int it = 0; it < 4; it++) {
            int idx = tid + 256 * it;                 // 0..1023 16B slots
            int r = idx >> 3, c = (idx & 7) * 8;
            int gm = m0 + r;
            const __half* srcA = g_zh + (size_t)gm * EHID + kc + c;
            int szA = (gm < E_EDGES) ? 16 : 0;        // zero-fill OOB rows
            asm volatile("cp.async.cg.shared.global [%0], [%1], 16, %2;"
                :: "r"(aoff + (uint32_t)(r * AS + c) * 2), "l"(srcA), "r"(szA));
            const __half* srcB = g_Wt + (size_t)(n0 + r) * EHID + kc + c;
            asm volatile("cp.async.cg.shared.global [%0], [%1], 16;"
                :: "r"(boff + (uint32_t)(r * AS + c) * 2), "l"(srcB));
        }
        asm volatile("cp.async.commit_group;" ::: "memory");
    }
}

// compute one BK=64 chunk from the given A/B smem buffers into acc
__device__ __forceinline__ void gemm_chunk(uint32_t sbA, uint32_t sbB,
                                           float (&acc)[2][8][4],
                                           int warp_m, int warp_n,
                                           int ar, int ac, int grp, int lig) {
    #pragma unroll
    for (int ks = 0; ks < BK / 16; ks++) {
        int k0 = ks * 16;
        uint32_t a[2][4];
        #pragma unroll
        for (int msub = 0; msub < 2; msub++) {
            uint32_t addr = sbA + ((warp_m * 32 + msub * 16 + ar) * AS + k0 + ac) * 2;
            asm volatile("ldmatrix.sync.aligned.m8n8.x4.shared.b16 {%0,%1,%2,%3}, [%4];"
                : "=r"(a[msub][0]), "=r"(a[msub][1]), "=r"(a[msub][2]), "=r"(a[msub][3])
                : "r"(addr));
        }
        uint32_t b[8][2];
        #pragma unroll
        for (int np = 0; np < 8; np += 2) {
            int row = warp_n * 64 + (np + (grp >> 1)) * 8 + lig;
            int col = k0 + (grp & 1) * 8;
            uint32_t addr = sbB + (uint32_t)(row * AS + col) * 2;
            asm volatile("ldmatrix.sync.aligned.m8n8.x4.shared.b16 {%0,%1,%2,%3}, [%4];"
                : "=r"(b[np][0]), "=r"(b[np][1]), "=r"(b[np+1][0]), "=r"(b[np+1][1])
                : "r"(addr));
        }
        #pragma unroll
        for (int msub = 0; msub < 2; msub++)
            #pragma unroll
            for (int nsub = 0; nsub < 8; nsub++) {
                asm volatile(
                    "mma.sync.aligned.m16n8k16.row.col.f32.f16.f16.f32 "
                    "{%0,%1,%2,%3}, {%4,%5,%6,%7}, {%8,%9}, {%0,%1,%2,%3};"
                    : "+f"(acc[msub][nsub][0]), "+f"(acc[msub][nsub][1]),
                      "+f"(acc[msub][nsub][2]), "+f"(acc[msub][nsub][3])
                    : "r"(a[msub][0]), "r"(a[msub][1]), "r"(a[msub][2]), "r"(a[msub][3]),
                      "r"(b[nsub][0]), "r"(b[nsub][1]));
            }
    }
}

__global__ void __launch_bounds__(256, 2)
k_gemm_hmma(const float* __restrict__ be2) {
    extern __shared__ char smem[];
    float*  bias_s = reinterpret_cast<float*>(smem + BIAS_OFF);
    __half* Cs     = reinterpret_cast<__half*>(smem + C_OFF);

    const int tid  = threadIdx.x;
    const int wid  = tid >> 5, lane = tid & 31;
    const int warp_m = wid >> 1;                  // 0..3  (32 rows each)
    const int warp_n = wid & 1;                   // 0..1  (64 cols each)
    const int ar  = lane & 15, ac = (lane >> 4) * 8;
    const int grp = lane >> 3, lig = lane & 7;
    const int qcol = (lane & 3) * 2;

    const uint32_t sb  = smem_to_u32(smem);
    const uint32_t sbC = sb + C_OFF;

    // prologue: issue loads for first tile
    {
        int t0 = blockIdx.x;
        issue_tile_loads(sb, tid, (t0 % M_TILES) * 128, (t0 / M_TILES) * 128);
    }

    for (int t = blockIdx.x; t < NTILES; t += NPERS) {
        const int m0 = (t % M_TILES) * 128;
        const int n0 = (t / M_TILES) * 128;

        // issue bias LDG early (latency hidden under compute)
        float breg = 0.0f;
        if (tid < 128) breg = be2[n0 + tid];

        float acc[2][8][4];
        #pragma unroll
        for (int i = 0; i < 2; i++)
            #pragma unroll
            for (int j = 0; j < 8; j++)
                #pragma unroll
                for (int q = 0; q < 4; q++) acc[i][j][q] = 0.0f;

        // chunk 0
        asm volatile("cp.async.wait_group 1;" ::: "memory");
        __syncthreads();
        gemm_chunk(sb + A0_OFF, sb + B0_OFF, acc, warp_m, warp_n, ar, ac, grp, lig);

        // chunk 1
        asm volatile("cp.async.wait_group 0;" ::: "memory");
        __syncthreads();
        gemm_chunk(sb + A1_OFF, sb + B1_OFF, acc, warp_m, warp_n, ar, ac, grp, lig);

        __syncthreads();          // all warps done reading stage buffers

        // issue NEXT tile's loads -- they proceed while we drain the epilogue
        int tn = t + NPERS;
        if (tn < NTILES)
            issue_tile_loads(sb, tid, (tn % M_TILES) * 128, (tn / M_TILES) * 128);

        // publish bias, then epilogue
        if (tid < 128) bias_s[tid] = breg;
        __syncthreads();

        float2 bfr[8];
        #pragma unroll
        for (int nsub = 0; nsub < 8; nsub++) {
            int lc = warp_n * 64 + nsub * 8 + qcol;
            bfr[nsub] = make_float2(bias_s[lc], bias_s[lc + 1]);
        }

        #pragma unroll
        for (int msub = 0; msub < 2; msub++) {
            #pragma unroll
            for (int np = 0; np < 8; np += 2) {
                int row_local = warp_m * 32 + msub * 16 + (grp & 1) * 8 + lig;
                int col_local = warp_n * 64 + (np + (grp >> 1)) * 8;
                uint32_t addr = sbC + (uint32_t)(row_local * CS + col_local) * 2;
                __half2 h0 = __floats2half2_rn(acc[msub][np][0]   + bfr[np].x,
                                               acc[msub][np][1]   + bfr[np].y);
                __half2 h1 = __floats2half2_rn(acc[msub][np][2]   + bfr[np].x,
                                               acc[msub][np][3]   + bfr[np].y);
                __half2 h2 = __floats2half2_rn(acc[msub][np+1][0] + bfr[np+1].x,
                                               acc[msub][np+1][1] + bfr[np+1].y);
                __half2 h3 = __floats2half2_rn(acc[msub][np+1][2] + bfr[np+1].x,
                                               acc[msub][np+1][3] + bfr[np+1].y);
                stmatrix_x4(addr,
                            *reinterpret_cast<uint32_t*>(&h0), *reinterpret_cast<uint32_t*>(&h1),
                            *reinterpret_cast<uint32_t*>(&h2), *reinterpret_cast<uint32_t*>(&h3));
            }
        }
        __syncthreads();

        // coalesced global stores: 128 rows x 16 uint4
        #pragma unroll
        for (int it = 0; it < 8; it++) {
            int idx = tid + 256 * it;                 // 0..2047
            int r = idx >> 4, c = (idx & 15) * 8;
            int gm = m0 + r;
            if (gm < E_EDGES) {
                uint4 v = *reinterpret_cast<const uint4*>(Cs + r * CS + c);
                *reinterpret_cast<uint4*>(g_ewh + (size_t)gm * N_EW + n0 + c) = v;
            }
        }
        __syncthreads();          // Cs fully drained before next tile's stmatrix
    }
}

// ---------------------------------------------------------------------------
// Kernel 4: zero the aggregation buffer (separate kernel measured faster than
// fusing the reset into k_relu -- R5 regression)
// ---------------------------------------------------------------------------
__global__ void k_zero() {
    int i = blockIdx.x * 256 + threadIdx.x;
    if (i < V_NODES * OUT_DIM) g_agg[i] = 0.0f;
}

// ---------------------------------------------------------------------------
// Kernel 5: msg[e] = h[src[e]] @ ew[e] (fp16 weights), atomic scatter to dst.
// One warp per edge. ReLU sparsity: zero h features -> skip the 128B ew row
// (warp-uniform predicate; predicated-off LDGs fetch nothing).
// ---------------------------------------------------------------------------
__global__ void __launch_bounds__(256)
k_msg(const int* __restrict__ src, const int* __restrict__ dst) {
    int g = threadIdx.x >> 5;                 // warp slot (edge) 0..7
    int o = threadIdx.x & 31;                 // half2 column index
    int e = blockIdx.x * 8 + g;
    __shared__ float hs[8][OUT_DIM];

    int s = src[e];
    hs[g][o]      = g_h[s * OUT_DIM + o];
    hs[g][o + 32] = g_h[s * OUT_DIM + o + 32];
    __syncwarp();

    const __half2* w = reinterpret_cast<const __half2*>(g_ewh + (size_t)e * N_EW) + o;
    float2 acc = make_float2(0.0f, 0.0f);
    #pragma unroll
    for (int i = 0; i < OUT_DIM; i++) {
        float hv = hs[g][i];
        if (hv != 0.0f) {                      // warp-uniform skip of zero rows
            float2 wv = __half22float2(w[i * 32]);
            acc.x = fmaf(hv, wv.x, acc.x);
            acc.y = fmaf(hv, wv.y, acc.y);
        }
    }
    float* a = &g_agg[(size_t)dst[e] * OUT_DIM + 2 * o];
    atomicAdd(a,     acc.x);
    atomicAdd(a + 1, acc.y);
}

// ---------------------------------------------------------------------------
// Kernel 6: h = relu(agg + bias); last step writes d_out
// ---------------------------------------------------------------------------
__global__ void k_relu(const float* __restrict__ bias, float* __restrict__ dout,
                       int last) {
    int i = blockIdx.x * 256 + threadIdx.x;
    if (i >= V_NODES * OUT_DIM) return;
    float v = fmaxf(g_agg[i] + bias[i & 63], 0.0f);
    if (last) dout[i] = v;
    else      g_h[i]  = v;
}

// ---------------------------------------------------------------------------
// Launch
// ---------------------------------------------------------------------------
extern "C" void kernel_launch(void* const* d_in, const int* in_sizes, int n_in,
                              void* d_out, int out_size) {
    const float* nf   = (const float*)d_in[0];
    const float* ef   = (const float*)d_in[1];
    const int*   src  = (const int*)  d_in[2];
    const int*   dst  = (const int*)  d_in[3];
    const float* Wp   = (const float*)d_in[4];
    const float* bp   = (const float*)d_in[5];
    const float* We1  = (const float*)d_in[6];
    const float* be1  = (const float*)d_in[7];
    const float* We2  = (const float*)d_in[8];
    const float* be2  = (const float*)d_in[9];
    const float* bias = (const float*)d_in[10];
    float* out = (float*)d_out;

    (void)in_sizes; (void)n_in; (void)out_size;

    cudaFuncSetAttribute(k_gemm_hmma, cudaFuncAttributeMaxDynamicSharedMemorySize,
                         GEMM_SMEM);

    k_project<<<V_NODES, OUT_DIM>>>(nf, Wp, bp);
    k_edge1<<<E_EDGES, EHID>>>(ef, We1, be1);
    k_transpose<<<N_EW, EHID>>>(We2);

    k_gemm_hmma<<<NPERS, 256, GEMM_SMEM>>>(be2);

    int nelem_blocks = (V_NODES * OUT_DIM + 255) / 256;  // 6250
    for (int t = 0; t < NSTEPS; t++) {
        k_zero<<<nelem_blocks, 256>>>();
        k_msg<<<E_EDGES / 8, 256>>>(src, dst);
        k_relu<<<nelem_blocks, 256>>>(bias, out, t == NSTEPS - 1 ? 1 : 0);
    }
}

// round 14
// speedup vs baseline: 1.1206x; 1.1206x over previous
#include <cuda_runtime.h>
#include <cuda_bf16.h>
#include <cuda_fp16.h>
#include <cstdint>
#include <cstddef>

// Problem constants
#define V_NODES   25000
#define E_EDGES   100000
#define NODE_IN   74
#define EDGE_IN   12
#define OUT_DIM   64
#define EHID      128
#define NSTEPS    6
#define N_EW      4096        // OUT*OUT

// ---------------------------------------------------------------------------
// Scratch (__device__ globals -- the sanctioned scratch mechanism)
// ---------------------------------------------------------------------------
__device__ float  g_h  [V_NODES * OUT_DIM];                 // 6.4 MB
__device__ float  g_agg[V_NODES * OUT_DIM];                 // 6.4 MB
__device__ __align__(256) __half g_zh [E_EDGES * EHID];     // 25.6 MB  z (fp16)
__device__ __align__(256) __half g_Wt [N_EW * EHID];        // 1 MB     We2^T (fp16)
__device__ __align__(256) __half g_ewh[(size_t)E_EDGES * N_EW]; // 819 MB ew (fp16)

__device__ __forceinline__ uint32_t smem_to_u32(const void* p) {
    uint32_t a;
    asm("{ .reg .u64 t; cvta.to.shared.u64 t, %1; cvt.u32.u64 %0, t; }" : "=r"(a) : "l"(p));
    return a;
}

// ---------------------------------------------------------------------------
// Kernel 1: h = relu(node_feats @ Wp + bp)      [25000 x 74] @ [74 x 64]
// ---------------------------------------------------------------------------
__global__ void k_project(const float* __restrict__ nf,
                          const float* __restrict__ Wp,
                          const float* __restrict__ bp) {
    int v = blockIdx.x;
    int o = threadIdx.x;                 // 64 threads
    __shared__ float s[NODE_IN];
    for (int i = o; i < NODE_IN; i += OUT_DIM) s[i] = nf[v * NODE_IN + i];
    __syncthreads();
    float acc = bp[o];
    #pragma unroll
    for (int i = 0; i < NODE_IN; i++) acc = fmaf(s[i], Wp[i * OUT_DIM + o], acc);
    g_h[v * OUT_DIM + o] = fmaxf(acc, 0.0f);
}

// ---------------------------------------------------------------------------
// Kernel 2: z = relu(edge_feats @ We1 + be1) -> fp16    [100000 x 12] @ [12 x 128]
// ---------------------------------------------------------------------------
__global__ void k_edge1(const float* __restrict__ ef,
                        const float* __restrict__ We1,
                        const float* __restrict__ be1) {
    int e = blockIdx.x;
    int k = threadIdx.x;                 // 128 threads
    __shared__ float s[EDGE_IN];
    if (k < EDGE_IN) s[k] = ef[e * EDGE_IN + k];
    __syncthreads();
    float acc = be1[k];
    #pragma unroll
    for (int j = 0; j < EDGE_IN; j++) acc = fmaf(s[j], We1[j * EHID + k], acc);
    g_zh[e * EHID + k] = __float2half_rn(fmaxf(acc, 0.0f));
}

// ---------------------------------------------------------------------------
// Kernel 2b: Wt[n][k] = (half)We2[k][n]   (tiny one-time transpose, 1 MB out)
// ---------------------------------------------------------------------------
__global__ void k_transpose(const float* __restrict__ We2) {
    int n = blockIdx.x;                  // 4096
    int k = threadIdx.x;                 // 128
    g_Wt[n * EHID + k] = __float2half_rn(We2[(size_t)k * N_EW + n]);
}

// ---------------------------------------------------------------------------
// Kernel 3: HMMA fp16 GEMM  ew = z @ We2 + be2 -> fp16   (R7 structure, the
// measured-fastest variant; R8's persistent loop regressed and was reverted)
// CTA tile 128x128, K=128 in 2 chunks of 64, double-buffered via cp.async.cg:
// both chunks' loads issued up front (L1-bypass, no register staging), then
// wait_group 1 -> compute chunk0, wait_group 0 -> compute chunk1.
// 8 warps in 4(M) x 2(N); warp tile 32x64. B fragments via paired ldmatrix.x4.
// Epilogue: bias-add in regs, stmatrix -> smem (reuses stage-0 region),
// coalesced uint4 STG.CS (evict-first: ew is write-once streaming, keep z/Wt
// resident in L2). Smem 74.25 KB -> 2 CTAs/SM.
// ---------------------------------------------------------------------------
#define BK        64
#define AS        72                               // halves per smem row (+pad)
#define STAGE_SZ  (128 * AS * 2)                   // 18432 B (one A or B buffer)
#define A0_OFF    0
#define B0_OFF    STAGE_SZ
#define A1_OFF    (2 * STAGE_SZ)
#define B1_OFF    (3 * STAGE_SZ)
#define BIAS_OFF  (4 * STAGE_SZ)                   // 73728
#define GEMM_SMEM (BIAS_OFF + 512)
#define CS        136                              // epilogue stride (halves)

__device__ __forceinline__ void stmatrix_x4(uint32_t addr, uint32_t r0, uint32_t r1,
                                            uint32_t r2, uint32_t r3) {
    asm volatile("stmatrix.sync.aligned.m8n8.x4.shared.b16 [%0], {%1,%2,%3,%4};"
                 :: "r"(addr), "r"(r0), "r"(r1), "r"(r2), "r"(r3) : "memory");
}

// compute one BK=64 chunk from the given A/B smem buffers into acc
__device__ __forceinline__ void gemm_chunk(uint32_t sbA, uint32_t sbB,
                                           float (&acc)[2][8][4],
                                           int warp_m, int warp_n,
                                           int ar, int ac, int grp, int lig) {
    #pragma unroll
    for (int ks = 0; ks < BK / 16; ks++) {
        int k0 = ks * 16;
        uint32_t a[2][4];
        #pragma unroll
        for (int msub = 0; msub < 2; msub++) {
            uint32_t addr = sbA + ((warp_m * 32 + msub * 16 + ar) * AS + k0 + ac) * 2;
            asm volatile("ldmatrix.sync.aligned.m8n8.x4.shared.b16 {%0,%1,%2,%3}, [%4];"
                : "=r"(a[msub][0]), "=r"(a[msub][1]), "=r"(a[msub][2]), "=r"(a[msub][3])
                : "r"(addr));
        }
        uint32_t b[8][2];
        #pragma unroll
        for (int np = 0; np < 8; np += 2) {
            int row = warp_n * 64 + (np + (grp >> 1)) * 8 + lig;
            int col = k0 + (grp & 1) * 8;
            uint32_t addr = sbB + (uint32_t)(row * AS + col) * 2;
            asm volatile("ldmatrix.sync.aligned.m8n8.x4.shared.b16 {%0,%1,%2,%3}, [%4];"
                : "=r"(b[np][0]), "=r"(b[np][1]), "=r"(b[np+1][0]), "=r"(b[np+1][1])
                : "r"(addr));
        }
        #pragma unroll
        for (int msub = 0; msub < 2; msub++)
            #pragma unroll
            for (int nsub = 0; nsub < 8; nsub++) {
                asm volatile(
                    "mma.sync.aligned.m16n8k16.row.col.f32.f16.f16.f32 "
                    "{%0,%1,%2,%3}, {%4,%5,%6,%7}, {%8,%9}, {%0,%1,%2,%3};"
                    : "+f"(acc[msub][nsub][0]), "+f"(acc[msub][nsub][1]),
                      "+f"(acc[msub][nsub][2]), "+f"(acc[msub][nsub][3])
                    : "r"(a[msub][0]), "r"(a[msub][1]), "r"(a[msub][2]), "r"(a[msub][3]),
                      "r"(b[nsub][0]), "r"(b[nsub][1]));
            }
    }
}

__global__ void __launch_bounds__(256, 2)
k_gemm_hmma(const float* __restrict__ be2) {
    extern __shared__ char smem[];
    float* bias_s = reinterpret_cast<float*>(smem + BIAS_OFF);

    const int tid  = threadIdx.x;
    const int wid  = tid >> 5, lane = tid & 31;
    const int warp_m = wid >> 1;                  // 0..3  (32 rows each)
    const int warp_n = wid & 1;                   // 0..1  (64 cols each)
    const int m0 = blockIdx.y * 128;
    const int n0 = blockIdx.x * 128;

    if (tid < 128) bias_s[tid] = be2[n0 + tid];

    const uint32_t sb = smem_to_u32(smem);

    // --- issue BOTH K-chunks via cp.async.cg (16B, L1-bypass) ---
    #pragma unroll
    for (int stage = 0; stage < 2; stage++) {
        int kc = stage * BK;
        uint32_t aoff = sb + (stage ? A1_OFF : A0_OFF);
        uint32_t boff = sb + (stage ? B1_OFF : B0_OFF);
        #pragma unroll
        for (int it = 0; it < 4; it++) {
            int idx = tid + 256 * it;                 // 0..1023 16B slots
            int r = idx >> 3, c = (idx & 7) * 8;
            int gm = m0 + r;
            const __half* srcA = g_zh + (size_t)gm * EHID + kc + c;
            int szA = (gm < E_EDGES) ? 16 : 0;        // zero-fill OOB rows
            asm volatile("cp.async.cg.shared.global [%0], [%1], 16, %2;"
                :: "r"(aoff + (uint32_t)(r * AS + c) * 2), "l"(srcA), "r"(szA));
            const __half* srcB = g_Wt + (size_t)(n0 + r) * EHID + kc + c;
            asm volatile("cp.async.cg.shared.global [%0], [%1], 16;"
                :: "r"(boff + (uint32_t)(r * AS + c) * 2), "l"(srcB));
        }
        asm volatile("cp.async.commit_group;" ::: "memory");
    }

    float acc[2][8][4];
    #pragma unroll
    for (int i = 0; i < 2; i++)
        #pragma unroll
        for (int j = 0; j < 8; j++)
            #pragma unroll
            for (int q = 0; q < 4; q++) acc[i][j][q] = 0.0f;

    const int ar  = lane & 15, ac = (lane >> 4) * 8;   // A ldmatrix addr parts
    const int grp = lane >> 3, lig = lane & 7;         // B x4 group decomposition

    // --- chunk 0 ---
    asm volatile("cp.async.wait_group 1;" ::: "memory");
    __syncthreads();
    gemm_chunk(sb + A0_OFF, sb + B0_OFF, acc, warp_m, warp_n, ar, ac, grp, lig);

    // --- chunk 1 ---
    asm volatile("cp.async.wait_group 0;" ::: "memory");
    __syncthreads();
    gemm_chunk(sb + A1_OFF, sb + B1_OFF, acc, warp_m, warp_n, ar, ac, grp, lig);

    // --- epilogue: bias-add in regs, stmatrix to smem, coalesced stores ---
    const int qcol = (lane & 3) * 2;
    float2 bfr[8];
    #pragma unroll
    for (int nsub = 0; nsub < 8; nsub++) {
        int lc = warp_n * 64 + nsub * 8 + qcol;
        bfr[nsub] = make_float2(bias_s[lc], bias_s[lc + 1]);
    }
    __syncthreads();        // all warps done with chunk-0/1 buffers + bias reads

    __half* Cs = reinterpret_cast<__half*>(smem);    // 128 x 136 halves (34.8 KB)
    uint32_t sbC = sb;

    #pragma unroll
    for (int msub = 0; msub < 2; msub++) {
        #pragma unroll
        for (int np = 0; np < 8; np += 2) {
            int row_local = warp_m * 32 + msub * 16 + (grp & 1) * 8 + lig;
            int col_local = warp_n * 64 + (np + (grp >> 1)) * 8;
            uint32_t addr = sbC + (uint32_t)(row_local * CS + col_local) * 2;
            __half2 h0 = __floats2half2_rn(acc[msub][np][0]   + bfr[np].x,
                                           acc[msub][np][1]   + bfr[np].y);
            __half2 h1 = __floats2half2_rn(acc[msub][np][2]   + bfr[np].x,
                                           acc[msub][np][3]   + bfr[np].y);
            __half2 h2 = __floats2half2_rn(acc[msub][np+1][0] + bfr[np+1].x,
                                           acc[msub][np+1][1] + bfr[np+1].y);
            __half2 h3 = __floats2half2_rn(acc[msub][np+1][2] + bfr[np+1].x,
                                           acc[msub][np+1][3] + bfr[np+1].y);
            stmatrix_x4(addr,
                        *reinterpret_cast<uint32_t*>(&h0), *reinterpret_cast<uint32_t*>(&h1),
                        *reinterpret_cast<uint32_t*>(&h2), *reinterpret_cast<uint32_t*>(&h3));
        }
    }
    __syncthreads();

    // Coalesced global stores: 128 rows x 16 uint4, evict-first (write-once stream)
    #pragma unroll
    for (int it = 0; it < 8; it++) {
        int idx = tid + 256 * it;                 // 0..2047
        int r = idx >> 4, c = (idx & 15) * 8;
        int gm = m0 + r;
        if (gm < E_EDGES) {
            uint4 v = *reinterpret_cast<const uint4*>(Cs + r * CS + c);
            __stcs(reinterpret_cast<uint4*>(g_ewh + (size_t)gm * N_EW + n0 + c), v);
        }
    }
}

// ---------------------------------------------------------------------------
// Kernel 4: zero the aggregation buffer (separate kernel measured faster than
// fusing the reset into k_relu -- R5 regression)
// ---------------------------------------------------------------------------
__global__ void k_zero() {
    int i = blockIdx.x * 256 + threadIdx.x;
    if (i < V_NODES * OUT_DIM) g_agg[i] = 0.0f;
}

// ---------------------------------------------------------------------------
// Kernel 5: msg[e] = h[src[e]] @ ew[e] (fp16 weights), atomic scatter to dst.
// One warp per edge. ReLU sparsity: zero h features -> skip the 128B ew row
// (warp-uniform predicate; predicated-off LDGs fetch nothing). ew reads use
// __ldcs (evict-first): each line read exactly once per step, keeps g_h/g_agg
// resident in L2.
// ---------------------------------------------------------------------------
__global__ void __launch_bounds__(256)
k_msg(const int* __restrict__ src, const int* __restrict__ dst) {
    int g = threadIdx.x >> 5;                 // warp slot (edge) 0..7
    int o = threadIdx.x & 31;                 // half2 column index
    int e = blockIdx.x * 8 + g;
    __shared__ float hs[8][OUT_DIM];

    int s = src[e];
    hs[g][o]      = g_h[s * OUT_DIM + o];
    hs[g][o + 32] = g_h[s * OUT_DIM + o + 32];
    __syncwarp();

    const __half2* w = reinterpret_cast<const __half2*>(g_ewh + (size_t)e * N_EW) + o;
    float2 acc = make_float2(0.0f, 0.0f);
    #pragma unroll
    for (int i = 0; i < OUT_DIM; i++) {
        float hv = hs[g][i];
        if (hv != 0.0f) {                      // warp-uniform skip of zero rows
            __half2 wh = __ldcs(w + i * 32);
            float2 wv = __half22float2(wh);
            acc.x = fmaf(hv, wv.x, acc.x);
            acc.y = fmaf(hv, wv.y, acc.y);
        }
    }
    float* a = &g_agg[(size_t)dst[e] * OUT_DIM + 2 * o];
    atomicAdd(a,     acc.x);
    atomicAdd(a + 1, acc.y);
}

// ---------------------------------------------------------------------------
// Kernel 6: h = relu(agg + bias); last step writes d_out
// ---------------------------------------------------------------------------
__global__ void k_relu(const float* __restrict__ bias, float* __restrict__ dout,
                       int last) {
    int i = blockIdx.x * 256 + threadIdx.x;
    if (i >= V_NODES * OUT_DIM) return;
    float v = fmaxf(g_agg[i] + bias[i & 63], 0.0f);
    if (last) dout[i] = v;
    else      g_h[i]  = v;
}

// ---------------------------------------------------------------------------
// Launch
// ---------------------------------------------------------------------------
extern "C" void kernel_launch(void* const* d_in, const int* in_sizes, int n_in,
                              void* d_out, int out_size) {
    const float* nf   = (const float*)d_in[0];
    const float* ef   = (const float*)d_in[1];
    const int*   src  = (const int*)  d_in[2];
    const int*   dst  = (const int*)  d_in[3];
    const float* Wp   = (const float*)d_in[4];
    const float* bp   = (const float*)d_in[5];
    const float* We1  = (const float*)d_in[6];
    const float* be1  = (const float*)d_in[7];
    const float* We2  = (const float*)d_in[8];
    const float* be2  = (const float*)d_in[9];
    const float* bias = (const float*)d_in[10];
    float* out = (float*)d_out;

    (void)in_sizes; (void)n_in; (void)out_size;

    cudaFuncSetAttribute(k_gemm_hmma, cudaFuncAttributeMaxDynamicSharedMemorySize,
                         GEMM_SMEM);

    k_project<<<V_NODES, OUT_DIM>>>(nf, Wp, bp);
    k_edge1<<<E_EDGES, EHID>>>(ef, We1, be1);
    k_transpose<<<N_EW, EHID>>>(We2);

    dim3 gemm_grid(N_EW / 128, (E_EDGES + 127) / 128);   // (32, 782)
    k_gemm_hmma<<<gemm_grid, 256, GEMM_SMEM>>>(be2);

    int nelem_blocks = (V_NODES * OUT_DIM + 255) / 256;  // 6250
    for (int t = 0; t < NSTEPS; t++) {
        k_zero<<<nelem_blocks, 256>>>();
        k_msg<<<E_EDGES / 8, 256>>>(src, dst);
        k_relu<<<nelem_blocks, 256>>>(bias, out, t == NSTEPS - 1 ? 1 : 0);
    }
}